// round 11
// baseline (speedup 1.0000x reference)
#include <cuda_runtime.h>
#include <cuda_fp16.h>
#include <math.h>
#include <stdint.h>

// ---------------------------------------------------------------------------
// Mamba block: B=4, L=2048, dim=1024, d_inner=2048, d_state=16, K=4, dt_rank=64
// Baseline sm_103 PTX -> ldmatrix + mma.sync fp16 HMMA (fp32 accum).
// fp16 operands + fp16 intermediates; err ~1e-4 < 1e-3 gate.
// GEMM: 128x128x32 tile, 512 threads (warp tile 32x32), 4-stage cp.async,
//       __launch_bounds__(512,2) -> 32 warps/SM (GEMM was occupancy-bound:
//       measured tensor=29.6% at occ=19.6%).
// Scan: 2-pass segmented parallel linear recurrence.
// Prep: all weight transposes + rmsnorm fused into ONE launch.
// ---------------------------------------------------------------------------
#define BB      4
#define LL      2048
#define DIM     1024
#define DINNER  2048
#define DSTATE  16
#define DCONV   4
#define DTRANK  64
#define NTOK    (BB * LL)              // 8192
#define DBC_W   (DTRANK + 2 * DSTATE)  // 96
#define KSPLIT  4
#define NSEG    8
#define SEGLEN  (LL / NSEG)            // 256

// ---------------------------------------------------------------------------
// Scratch (device globals; zero-initialized)
// ---------------------------------------------------------------------------
__device__ __half g_xz[(size_t)NTOK * 2 * DINNER];
__device__ float  g_dbc[(size_t)NTOK * DBC_W];
__device__ float  g_dbcp[(size_t)KSPLIT * NTOK * 128];
__device__ __half g_delta[(size_t)NTOK * DINNER];
__device__ __half g_xn[(size_t)NTOK * DIM];
__device__ __half g_xi[(size_t)NTOK * DINNER];
__device__ __half g_dt[(size_t)NTOK * DTRANK];
__device__ __half g_g[(size_t)NTOK * DINNER];
__device__ float  g_segsum[(size_t)NSEG * BB * DINNER];
__device__ float  g_segc[(size_t)NSEG * BB * DINNER * DSTATE];
// transposed weights [N,K] fp16; x_proj padded to 128 rows (96..127 zero)
__device__ __half g_ipT[(size_t)(2 * DINNER) * DIM];
__device__ __half g_xpT[(size_t)128 * DINNER];
__device__ __half g_dwT[(size_t)DINNER * DTRANK];
__device__ __half g_opT[(size_t)DIM * DINNER];

// ---------------------------------------------------------------------------
// PTX helpers
// ---------------------------------------------------------------------------
__device__ __forceinline__ uint32_t smem_u32(const void* p) {
    uint32_t a;
    asm("{ .reg .u64 t; cvta.to.shared.u64 t, %1; cvt.u32.u64 %0, t; }" : "=r"(a) : "l"(p));
    return a;
}
__device__ __forceinline__ void cp16(uint32_t dst, const void* src) {
    asm volatile("cp.async.cg.shared.global [%0], [%1], 16;" :: "r"(dst), "l"(src));
}
#define CP_COMMIT() asm volatile("cp.async.commit_group;" ::: "memory")
#define CP_WAIT(n)  asm volatile("cp.async.wait_group %0;" :: "n"(n) : "memory")

#define LDSM4(r, a) \
    asm volatile("ldmatrix.sync.aligned.m8n8.x4.shared.b16 {%0,%1,%2,%3}, [%4];" \
        : "=r"((r)[0]), "=r"((r)[1]), "=r"((r)[2]), "=r"((r)[3]) : "r"(a))

#define MMA16816(d, a, b0, b1) \
    asm volatile("mma.sync.aligned.m16n8k16.row.col.f32.f16.f16.f32 " \
        "{%0,%1,%2,%3}, {%4,%5,%6,%7}, {%8,%9}, {%0,%1,%2,%3};" \
        : "+f"((d)[0]), "+f"((d)[1]), "+f"((d)[2]), "+f"((d)[3]) \
        : "r"((a)[0]), "r"((a)[1]), "r"((a)[2]), "r"((a)[3]), "r"(b0), "r"(b1))

// powers P[s] = E^(s+1) via repeated squaring
__device__ __forceinline__ void exp_powers(float E, float* P) {
    float E2 = E * E, E4 = E2 * E2, E8 = E4 * E4;
    P[0]=E;      P[1]=E2;      P[2]=E2*E;     P[3]=E4;
    P[4]=E4*E;   P[5]=E4*E2;   P[6]=E4*P[2];  P[7]=E8;
    P[8]=E8*E;   P[9]=E8*E2;   P[10]=E8*P[2]; P[11]=E8*E4;
    P[12]=E8*P[4]; P[13]=E8*P[5]; P[14]=E8*P[6]; P[15]=E8*E8;
}

// ---------------------------------------------------------------------------
// Fused prep: weight transposes (fp32 [R,C] -> fp16 [C,R]) + rmsnorm, one grid.
// Block ranges: [0,4096) ipT | [4096,4288) xpT | [4288,4416) dwT |
//               [4416,6464) opT | [6464,14656) rmsnorm token = bid-6464
// ---------------------------------------------------------------------------
__device__ __forceinline__ void transpose_tile(const float* __restrict__ W,
                                               __half* __restrict__ T,
                                               int R, int C, int cb, int rb) {
    __shared__ float t[32][33];
    const int tx = threadIdx.x & 31, ty = threadIdx.x >> 5;
    int c0 = cb * 32, r0 = rb * 32;
    int c = c0 + tx;
    for (int i = ty; i < 32; i += 8) {
        int r = r0 + i;
        if (r < R && c < C) t[i][tx] = W[(size_t)r * C + c];
    }
    __syncthreads();
    int k = r0 + tx;
    for (int i = ty; i < 32; i += 8) {
        int n = c0 + i;
        if (n < C && k < R)
            T[(size_t)n * R + k] = __float2half(t[tx][i]);
    }
}

__global__ void __launch_bounds__(256)
prep_kernel(const float* __restrict__ in_proj, const float* __restrict__ x_proj,
            const float* __restrict__ dt_w,    const float* __restrict__ out_proj,
            __half* __restrict__ ipT, __half* __restrict__ xpT,
            __half* __restrict__ dwT, __half* __restrict__ opT,
            const float* __restrict__ x, const float* __restrict__ rms_w,
            __half* __restrict__ xn) {
    int bid = blockIdx.x;
    if (bid < 4096) {
        transpose_tile(in_proj, ipT, DIM, 2 * DINNER, bid & 127, bid >> 7);
    } else if (bid < 4288) {
        int i = bid - 4096;
        transpose_tile(x_proj, xpT, DINNER, DBC_W, i % 3, i / 3);
    } else if (bid < 4416) {
        int i = bid - 4288;
        transpose_tile(dt_w, dwT, DTRANK, DINNER, i & 63, i >> 6);
    } else if (bid < 6464) {
        int i = bid - 4416;
        transpose_tile(out_proj, opT, DINNER, DIM, i & 31, i >> 5);
    } else {
        int t = bid - 6464;
        const float* xr = x + (size_t)t * DIM;
        float s = 0.f;
        for (int i = threadIdx.x; i < DIM; i += 256) { float v = xr[i]; s += v * v; }
        #pragma unroll
        for (int off = 16; off > 0; off >>= 1) s += __shfl_xor_sync(0xffffffffu, s, off);
        __shared__ float red[8];
        int wid = threadIdx.x >> 5;
        if ((threadIdx.x & 31) == 0) red[wid] = s;
        __syncthreads();
        __shared__ float sscale;
        if (threadIdx.x == 0) {
            float tot = 0.f;
            #pragma unroll
            for (int i = 0; i < 8; i++) tot += red[i];
            sscale = rsqrtf(tot * (1.0f / DIM) + 1e-5f);
        }
        __syncthreads();
        float scale = sscale;
        for (int i = threadIdx.x * 2; i < DIM; i += 512) {
            float2 v = *(const float2*)(xr + i);
            float2 wv = *(const float2*)(rms_w + i);
            *(__half2*)(xn + (size_t)t * DIM + i) =
                __floats2half2_rn(v.x * scale * wv.x, v.y * scale * wv.y);
        }
    }
}

// ---------------------------------------------------------------------------
// mma.sync fp16 GEMM: C[M,N] = A[M,K] @ B[N,K]^T, fp32 accumulate.
// 128x128x32 tile, 512 threads (16 warps: 4M x 4N, warp tile 32x32).
// 4-stage cp.async pipeline; __launch_bounds__(512,2) -> 2 CTAs/SM.
// kpz: per-blockIdx.z K offset (split-K); czs: per-z C offset (floats).
// MODE 0: fp32 out  1: softplus(+bias) -> fp16 out  2: +res -> fp32 out
// MODE 4: fp16 out
// ---------------------------------------------------------------------------
#define TSB   10240
#define STGB  (2 * TSB)
#define SMEM_GEMM (4 * STGB)          // 81920

template<int MODE>
__global__ void __launch_bounds__(512, 2)
mma_gemm(const __half* __restrict__ A, const __half* __restrict__ B,
         void* __restrict__ Cv, int N, int K, int ld,
         const float* __restrict__ extra, int kpz, size_t czs) {
    extern __shared__ char smem[];
    const uint32_t sb = smem_u32(smem);
    const int tid  = threadIdx.x;
    const int lane = tid & 31;
    const int wid  = tid >> 5;            // 0..15
    const int wm = (wid & 3) * 32;
    const int wn = (wid >> 2) * 32;
    const int row0 = blockIdx.y * 128;
    const int col0 = blockIdx.x * 128;
    const int nch = K >> 5;

    A += (size_t)blockIdx.z * kpz;
    B += (size_t)blockIdx.z * kpz;
    float*  Cf = (float*)Cv + blockIdx.z * czs;
    __half* Ch = (__half*)Cv;

    auto load_stage = [&](int st, int k0) {
        uint32_t base = sb + st * STGB;
        int r = tid >> 2, seg = tid & 3;   // 512 threads: 1 A + 1 B xfer each
        uint32_t d = base + r * 80 + seg * 16;
        cp16(d,       A + (size_t)(row0 + r) * ld + k0 + seg * 8);
        cp16(d + TSB, B + (size_t)(col0 + r) * ld + k0 + seg * 8);
    };

    float acc[2][4][4];
    #pragma unroll
    for (int mi = 0; mi < 2; mi++)
        #pragma unroll
        for (int ni = 0; ni < 4; ni++)
            #pragma unroll
            for (int q = 0; q < 4; q++) acc[mi][ni][q] = 0.f;

    const int lrow = lane & 15;
    const int lkb  = lane >> 4;

    load_stage(0, 0);                      CP_COMMIT();
    if (nch > 1) load_stage(1, 32);        CP_COMMIT();
    if (nch > 2) load_stage(2, 64);        CP_COMMIT();

    for (int kc = 0; kc < nch; kc++) {
        CP_WAIT(2);
        __syncthreads();
        if (kc + 3 < nch) load_stage((kc + 3) & 3, (kc + 3) << 5);
        CP_COMMIT();

        uint32_t base = sb + (kc & 3) * STGB;
        #pragma unroll
        for (int ks = 0; ks < 2; ks++) {
            uint32_t koff = (ks * 16 + lkb * 8) * 2;
            uint32_t ah[2][4];
            #pragma unroll
            for (int mi = 0; mi < 2; mi++)
                LDSM4(ah[mi], base + (wm + mi * 16 + lrow) * 80 + koff);
            uint32_t bf[2][4];
            #pragma unroll
            for (int p = 0; p < 2; p++)
                LDSM4(bf[p], base + TSB + (wn + p * 16 + lrow) * 80 + koff);
            #pragma unroll
            for (int mi = 0; mi < 2; mi++)
                #pragma unroll
                for (int p = 0; p < 2; p++)
                    #pragma unroll
                    for (int hb = 0; hb < 2; hb++)
                        MMA16816(acc[mi][p * 2 + hb], ah[mi], bf[p][hb], bf[p][hb + 2]);
        }
        __syncthreads();
    }

    const int rb = row0 + wm + (lane >> 2);
    const int cb = col0 + wn + (lane & 3) * 2;
    #pragma unroll
    for (int mi = 0; mi < 2; mi++)
        #pragma unroll
        for (int ni = 0; ni < 4; ni++) {
            int c = cb + ni * 8;
            if (c >= N) continue;
            #pragma unroll
            for (int half = 0; half < 2; half++) {
                int r = rb + mi * 16 + half * 8;
                float v0 = acc[mi][ni][half * 2 + 0];
                float v1 = acc[mi][ni][half * 2 + 1];
                if (MODE == 1) {
                    v0 += extra[c];     v1 += extra[c + 1];
                    v0 = (v0 > 20.f) ? v0 : log1pf(__expf(v0));
                    v1 = (v1 > 20.f) ? v1 : log1pf(__expf(v1));
                } else if (MODE == 2) {
                    const float2 res = *(const float2*)(extra + (size_t)r * N + c);
                    v0 += res.x; v1 += res.y;
                }
                if (MODE == 0 || MODE == 2)
                    *(float2*)(Cf + (size_t)r * N + c) = make_float2(v0, v1);
                else
                    *(__half2*)(Ch + (size_t)r * N + c) = __floats2half2_rn(v0, v1);
            }
        }
}

// ---------------------------------------------------------------------------
// Split-K reduce for dbc + dt fp16
// ---------------------------------------------------------------------------
__global__ void reduce_dbc(const float* __restrict__ part,
                           float* __restrict__ dbc,
                           __half* __restrict__ dt) {
    int i = blockIdx.x * blockDim.x + threadIdx.x;
    int r = i >> 7, c = i & 127;
    float s = 0.f;
    #pragma unroll
    for (int p = 0; p < KSPLIT; p++)
        s += part[(size_t)p * NTOK * 128 + i];
    if (c < DBC_W) dbc[(size_t)r * DBC_W + c] = s;
    if (c < DTRANK) dt[(size_t)r * DTRANK + c] = __float2half(s);
}

// ---------------------------------------------------------------------------
// Causal depthwise conv (K=4) + bias + SiLU: fp16 xz -> fp16 xi, 4 ch/thread
// ---------------------------------------------------------------------------
__global__ void conv_silu_kernel(const __half* __restrict__ xz,
                                 const float* __restrict__ conv_w,
                                 const float* __restrict__ conv_b,
                                 __half* __restrict__ xi) {
    size_t i4 = (size_t)blockIdx.x * blockDim.x + threadIdx.x;
    size_t idx = i4 * 4;
    if (idx >= (size_t)NTOK * DINNER) return;
    int c = (int)(idx % DINNER);
    int t = (int)(idx / DINNER);
    int l = t % LL;
    int tb = t - l;
    float4 acc = *(const float4*)(conv_b + c);
    const float4 w0 = *(const float4*)(conv_w + (c + 0) * DCONV);
    const float4 w1 = *(const float4*)(conv_w + (c + 1) * DCONV);
    const float4 w2 = *(const float4*)(conv_w + (c + 2) * DCONV);
    const float4 w3 = *(const float4*)(conv_w + (c + 3) * DCONV);
    const float wk[4][4] = {{w0.x, w0.y, w0.z, w0.w}, {w1.x, w1.y, w1.z, w1.w},
                            {w2.x, w2.y, w2.z, w2.w}, {w3.x, w3.y, w3.z, w3.w}};
    #pragma unroll
    for (int k = 0; k < DCONV; k++) {
        int ls = l - (DCONV - 1) + k;
        if (ls >= 0) {
            uint2 p = *(const uint2*)(xz + (size_t)(tb + ls) * (2 * DINNER) + c);
            __half2 v01 = *(__half2*)&p.x;
            __half2 v23 = *(__half2*)&p.y;
            acc.x += __half2float(__low2half(v01))  * wk[0][k];
            acc.y += __half2float(__high2half(v01)) * wk[1][k];
            acc.z += __half2float(__low2half(v23))  * wk[2][k];
            acc.w += __half2float(__high2half(v23)) * wk[3][k];
        }
    }
    float s0 = acc.x / (1.f + __expf(-acc.x));
    float s1 = acc.y / (1.f + __expf(-acc.y));
    float s2 = acc.z / (1.f + __expf(-acc.z));
    float s3 = acc.w / (1.f + __expf(-acc.w));
    __half2 h01 = __floats2half2_rn(s0, s1);
    __half2 h23 = __floats2half2_rn(s2, s3);
    uint2 pack;
    pack.x = *(uint32_t*)&h01;
    pack.y = *(uint32_t*)&h23;
    *(uint2*)(xi + idx) = pack;
}

// ---------------------------------------------------------------------------
// Scan pass 1: per (channel, segment<NSEG-1) compute segment transfer:
//   sd = sum(delta), cvec[s] = recurrence from h=0 over SEGLEN steps.
// ---------------------------------------------------------------------------
#define SCHUNK 16
#define SSTG1  5120                    // delta 2K | xi 2K | B 1K
__global__ __launch_bounds__(64, 1)
void scan_pass1(const float* __restrict__ dbc,
                const __half* __restrict__ delta,
                const __half* __restrict__ xi,
                const float* __restrict__ A_log,
                float* __restrict__ segsum,
                float* __restrict__ segc) {
    __shared__ char sbuf[4 * SSTG1];
    const uint32_t sb = smem_u32(sbuf);
    const int seg   = blockIdx.y;
    const int b     = blockIdx.x >> 5;
    const int cbase = (blockIdx.x & 31) * 64;
    const int tid   = threadIdx.x;
    const int c     = cbase + tid;
    const size_t tok0 = (size_t)b * LL + (size_t)seg * SEGLEN;

    float A[DSTATE];
    #pragma unroll
    for (int s = 0; s < DSTATE; s++) A[s] = -__expf(A_log[c * DSTATE + s]);
    const float a1 = A[0];
    bool pat = true;
    #pragma unroll
    for (int s = 0; s < DSTATE; s++)
        pat = pat && (fabsf(A[s] - (float)(s + 1) * a1) <= 1e-5f * fabsf(A[s]));

    float h[DSTATE];
    #pragma unroll
    for (int s = 0; s < DSTATE; s++) h[s] = 0.f;
    float sd = 0.f;

    auto stage_load = [&](int st, int l0) {
        uint32_t base = sb + st * SSTG1;
        #pragma unroll
        for (int u0 = 0; u0 < 5; u0++) {
            int u = u0 * 64 + tid;
            uint32_t dst; const void* src;
            if (u < 128) {               // delta fp16 [16][64]
                int r = u >> 3, s = u & 7;
                dst = base + r * 128 + s * 16;
                src = delta + (tok0 + l0 + r) * DINNER + cbase + s * 8;
            } else if (u < 256) {        // xi fp16 [16][64]
                int v = u - 128; int r = v >> 3, s = v & 7;
                dst = base + 2048 + r * 128 + s * 16;
                src = xi + (tok0 + l0 + r) * DINNER + cbase + s * 8;
            } else {                     // B fp32 [16][16]
                int v = u - 256; int r = v >> 2, s = v & 3;
                dst = base + 4096 + r * 64 + s * 16;
                src = dbc + (tok0 + l0 + r) * DBC_W + DTRANK + s * 4;
            }
            cp16(dst, src);
        }
    };

    const int nch = SEGLEN / SCHUNK;   // 16
    stage_load(0, 0);          CP_COMMIT();
    stage_load(1, SCHUNK);     CP_COMMIT();
    stage_load(2, 2 * SCHUNK); CP_COMMIT();

    for (int ck = 0; ck < nch; ck++) {
        CP_WAIT(2);
        __syncthreads();
        if (ck + 3 < nch) stage_load((ck + 3) & 3, (ck + 3) * SCHUNK);
        CP_COMMIT();

        const char* base = sbuf + (ck & 3) * SSTG1;
        const __half* sd16 = (const __half*)(base);
        const __half* sxi  = (const __half*)(base + 2048);
        const float*  sB   = (const float*)(base + 4096);

        #pragma unroll 4
        for (int l = 0; l < SCHUNK; l++) {
            float d  = __half2float(sd16[l * 64 + tid]);
            float xv = __half2float(sxi[l * 64 + tid]);
            const float* Bv = sB + l * 16;
            float dx = d * xv;
            if (pat) {
                float P[DSTATE];
                exp_powers(__expf(d * a1), P);
                #pragma unroll
                for (int s = 0; s < DSTATE; s++)
                    h[s] = P[s] * h[s] + dx * Bv[s];
            } else {
                #pragma unroll
                for (int s = 0; s < DSTATE; s++)
                    h[s] = __expf(d * A[s]) * h[s] + dx * Bv[s];
            }
            sd += d;
        }
        __syncthreads();
    }

    size_t bc = (size_t)seg * BB * DINNER + (size_t)b * DINNER + c;
    segsum[bc] = sd;
    #pragma unroll
    for (int s = 0; s < DSTATE; s++)
        segc[bc * DSTATE + s] = h[s];
}

// ---------------------------------------------------------------------------
// Scan pass 2: fold prefix segments (closed-form via exp(A*sd_j)), then run
// SEGLEN steps emitting gated output.  Fuses D skip + silu(z) gate.
// ---------------------------------------------------------------------------
#define SSTG2  8192                    // delta 2K | z 2K | xi 2K | bc 2K
__global__ __launch_bounds__(64, 1)
void scan_pass2(const float* __restrict__ dbc,
                const __half* __restrict__ delta,
                const __half* __restrict__ xi,
                const __half* __restrict__ xz,
                const float* __restrict__ A_log,
                const float* __restrict__ Dp,
                const float* __restrict__ segsum,
                const float* __restrict__ segc,
                __half* __restrict__ gout) {
    __shared__ char sbuf[4 * SSTG2];
    const uint32_t sb = smem_u32(sbuf);
    const int seg   = blockIdx.y;
    const int b     = blockIdx.x >> 5;
    const int cbase = (blockIdx.x & 31) * 64;
    const int tid   = threadIdx.x;
    const int c     = cbase + tid;
    const size_t tok0 = (size_t)b * LL + (size_t)seg * SEGLEN;

    float A[DSTATE];
    #pragma unroll
    for (int s = 0; s < DSTATE; s++) A[s] = -__expf(A_log[c * DSTATE + s]);
    const float a1 = A[0];
    bool pat = true;
    #pragma unroll
    for (int s = 0; s < DSTATE; s++)
        pat = pat && (fabsf(A[s] - (float)(s + 1) * a1) <= 1e-5f * fabsf(A[s]));
    const float Dv = Dp[c];

    // prologue: fold segments 0..seg-1
    float h[DSTATE];
    #pragma unroll
    for (int s = 0; s < DSTATE; s++) h[s] = 0.f;
    for (int j = 0; j < seg; j++) {
        size_t bc = (size_t)j * BB * DINNER + (size_t)b * DINNER + c;
        float sdj = segsum[bc];
        if (pat) {
            float P[DSTATE];
            exp_powers(__expf(sdj * a1), P);
            #pragma unroll
            for (int s = 0; s < DSTATE; s++)
                h[s] = P[s] * h[s] + segc[bc * DSTATE + s];
        } else {
            #pragma unroll
            for (int s = 0; s < DSTATE; s++)
                h[s] = __expf(sdj * A[s]) * h[s] + segc[bc * DSTATE + s];
        }
    }

    auto stage_load = [&](int st, int l0) {
        uint32_t base = sb + st * SSTG2;
        #pragma unroll
        for (int u0 = 0; u0 < 8; u0++) {
            int u = u0 * 64 + tid;
            uint32_t dst; const void* src;
            if (u < 128) {               // delta fp16
                int r = u >> 3, s = u & 7;
                dst = base + r * 128 + s * 16;
                src = delta + (tok0 + l0 + r) * DINNER + cbase + s * 8;
            } else if (u < 256) {        // z fp16 (xz second half)
                int v = u - 128; int r = v >> 3, s = v & 7;
                dst = base + 2048 + r * 128 + s * 16;
                src = xz + (tok0 + l0 + r) * (2 * DINNER) + DINNER + cbase + s * 8;
            } else if (u < 384) {        // xi fp16
                int v = u - 256; int r = v >> 3, s = v & 7;
                dst = base + 4096 + r * 128 + s * 16;
                src = xi + (tok0 + l0 + r) * DINNER + cbase + s * 8;
            } else {                     // bc fp32 [16][32]
                int v = u - 384; int r = v >> 3, s = v & 7;
                dst = base + 6144 + r * 128 + s * 16;
                src = dbc + (tok0 + l0 + r) * DBC_W + DTRANK + s * 4;
            }
            cp16(dst, src);
        }
    };

    const int nch = SEGLEN / SCHUNK;   // 16
    stage_load(0, 0);          CP_COMMIT();
    stage_load(1, SCHUNK);     CP_COMMIT();
    stage_load(2, 2 * SCHUNK); CP_COMMIT();

    for (int ck = 0; ck < nch; ck++) {
        CP_WAIT(2);
        __syncthreads();
        if (ck + 3 < nch) stage_load((ck + 3) & 3, (ck + 3) * SCHUNK);
        CP_COMMIT();

        const char* base = sbuf + (ck & 3) * SSTG2;
        const __half* sd16 = (const __half*)(base);
        const __half* sz   = (const __half*)(base + 2048);
        const __half* sxi  = (const __half*)(base + 4096);
        const float*  sbc  = (const float*)(base + 6144);
        const int l0 = ck * SCHUNK;

        #pragma unroll 4
        for (int l = 0; l < SCHUNK; l++) {
            float d  = __half2float(sd16[l * 64 + tid]);
            float zv = __half2float(sz[l * 64 + tid]);
            float xv = __half2float(sxi[l * 64 + tid]);
            const float* Bv = sbc + l * 32;
            const float* Cv = Bv + DSTATE;
            float dx = d * xv;
            float y = 0.f;
            if (pat) {
                float P[DSTATE];
                exp_powers(__expf(d * a1), P);
                #pragma unroll
                for (int s = 0; s < DSTATE; s++) {
                    h[s] = P[s] * h[s] + dx * Bv[s];
                    y = fmaf(h[s], Cv[s], y);
                }
            } else {
                #pragma unroll
                for (int s = 0; s < DSTATE; s++) {
                    h[s] = __expf(d * A[s]) * h[s] + dx * Bv[s];
                    y = fmaf(h[s], Cv[s], y);
                }
            }
            float g  = y + xv * Dv;
            float sg = zv / (1.f + __expf(-zv));
            gout[(tok0 + l0 + l) * DINNER + c] = __float2half(g * sg);
        }
        __syncthreads();
    }
}

// ---------------------------------------------------------------------------
// Launch
// ---------------------------------------------------------------------------
extern "C" void kernel_launch(void* const* d_in, const int* in_sizes, int n_in,
                              void* d_out, int out_size) {
    const float* x        = (const float*)d_in[0];
    const float* rms_w    = (const float*)d_in[1];
    const float* in_proj  = (const float*)d_in[2];
    const float* conv_w   = (const float*)d_in[3];
    const float* conv_b   = (const float*)d_in[4];
    const float* x_proj   = (const float*)d_in[5];
    const float* dt_w     = (const float*)d_in[6];
    const float* dt_b     = (const float*)d_in[7];
    const float* A_log    = (const float*)d_in[8];
    const float* Dp       = (const float*)d_in[9];
    const float* out_proj = (const float*)d_in[10];
    float* out = (float*)d_out;

    float *dbc, *dbcp, *segsum, *segc;
    __half *xz, *delta, *xn, *xi, *dt, *gg, *ipT, *xpT, *dwT, *opT;
    cudaGetSymbolAddress((void**)&xz,     g_xz);
    cudaGetSymbolAddress((void**)&dbc,    g_dbc);
    cudaGetSymbolAddress((void**)&dbcp,   g_dbcp);
    cudaGetSymbolAddress((void**)&delta,  g_delta);
    cudaGetSymbolAddress((void**)&xn,     g_xn);
    cudaGetSymbolAddress((void**)&xi,     g_xi);
    cudaGetSymbolAddress((void**)&dt,     g_dt);
    cudaGetSymbolAddress((void**)&gg,     g_g);
    cudaGetSymbolAddress((void**)&segsum, g_segsum);
    cudaGetSymbolAddress((void**)&segc,   g_segc);
    cudaGetSymbolAddress((void**)&ipT,    g_ipT);
    cudaGetSymbolAddress((void**)&xpT,    g_xpT);
    cudaGetSymbolAddress((void**)&dwT,    g_dwT);
    cudaGetSymbolAddress((void**)&opT,    g_opT);

    cudaFuncSetAttribute(mma_gemm<0>, cudaFuncAttributeMaxDynamicSharedMemorySize, SMEM_GEMM);
    cudaFuncSetAttribute(mma_gemm<1>, cudaFuncAttributeMaxDynamicSharedMemorySize, SMEM_GEMM);
    cudaFuncSetAttribute(mma_gemm<2>, cudaFuncAttributeMaxDynamicSharedMemorySize, SMEM_GEMM);
    cudaFuncSetAttribute(mma_gemm<4>, cudaFuncAttributeMaxDynamicSharedMemorySize, SMEM_GEMM);

    // 0+1. fused prep: 4 weight transposes + rmsnorm in ONE launch
    prep_kernel<<<6464 + NTOK, 256>>>(in_proj, x_proj, dt_w, out_proj,
                                      ipT, xpT, dwT, opT, x, rms_w, xn);

    // 2. xz = xn @ in_proj -> fp16  [8192 x 4096], K=1024
    {
        dim3 grid(2 * DINNER / 128, NTOK / 128);
        mma_gemm<4><<<grid, 512, SMEM_GEMM>>>(xn, ipT, xz, 2 * DINNER, DIM, DIM,
                                              nullptr, 0, 0);
    }

    // 3. conv + silu -> xi fp16
    {
        size_t n4 = (size_t)NTOK * DINNER / 4;
        conv_silu_kernel<<<(unsigned)((n4 + 255) / 256), 256>>>(xz, conv_w, conv_b, xi);
    }

    // 4. dbc = xi @ x_proj: split-K x4 in ONE launch (gridDim.z) + reduce
    {
        const int kpart = DINNER / KSPLIT;   // 512
        dim3 grid(1, NTOK / 128, KSPLIT);
        mma_gemm<0><<<grid, 512, SMEM_GEMM>>>(xi, xpT, dbcp, 128, kpart, DINNER,
                                              nullptr, kpart, (size_t)NTOK * 128);
        reduce_dbc<<<NTOK * 128 / 256, 256>>>(dbcp, dbc, dt);
    }

    // 5. delta = softplus(dt @ dt_w + dt_b) -> fp16  [8192 x 2048], K=64
    {
        dim3 grid(DINNER / 128, NTOK / 128);
        mma_gemm<1><<<grid, 512, SMEM_GEMM>>>(dt, dwT, delta, DINNER, DTRANK, DTRANK,
                                              dt_b, 0, 0);
    }

    // 6. parallel selective scan (2 passes) + D skip + gate -> gated fp16
    {
        dim3 g1(BB * (DINNER / 64), NSEG - 1);
        scan_pass1<<<g1, 64>>>(dbc, delta, xi, A_log, segsum, segc);
        dim3 g2(BB * (DINNER / 64), NSEG);
        scan_pass2<<<g2, 64>>>(dbc, delta, xi, xz, A_log, Dp, segsum, segc, gg);
    }

    // 7. out = x + gated @ out_proj  [8192 x 1024], K=2048
    {
        dim3 grid(DIM / 128, NTOK / 128);
        mma_gemm<2><<<grid, 512, SMEM_GEMM>>>(gg, opT, out, DIM, DINNER, DINNER,
                                              x, 0, 0);
    }
}

// round 12
// speedup vs baseline: 1.0506x; 1.0506x over previous
#include <cuda_runtime.h>
#include <cuda_fp16.h>
#include <math.h>
#include <stdint.h>

// ---------------------------------------------------------------------------
// Mamba block: B=4, L=2048, dim=1024, d_inner=2048, d_state=16, K=4, dt_rank=64
// Baseline sm_103 PTX -> ldmatrix + mma.sync fp16 HMMA (fp32 accum).
// fp16 operands + fp16 intermediates; err ~1e-4 < 1e-3 gate.
// GEMM: 128x128x32 tile, 256 threads, 4-stage cp.async (R10 proven config;
//       R11 showed GEMM is effective-BW bound, occupancy-invariant).
// Scan: 2-pass segmented parallel recurrence, 128-thread blocks.
// GEMM1 epilogue pre-applies silu to the z half.
// ---------------------------------------------------------------------------
#define BB      4
#define LL      2048
#define DIM     1024
#define DINNER  2048
#define DSTATE  16
#define DCONV   4
#define DTRANK  64
#define NTOK    (BB * LL)              // 8192
#define DBC_W   (DTRANK + 2 * DSTATE)  // 96
#define KSPLIT  4
#define NSEG    8
#define SEGLEN  (LL / NSEG)            // 256

// ---------------------------------------------------------------------------
// Scratch (device globals; zero-initialized)
// ---------------------------------------------------------------------------
__device__ __half g_xz[(size_t)NTOK * 2 * DINNER];       // z half stores silu(z)
__device__ float  g_dbc[(size_t)NTOK * DBC_W];
__device__ float  g_dbcp[(size_t)KSPLIT * NTOK * 128];
__device__ __half g_delta[(size_t)NTOK * DINNER];
__device__ __half g_xn[(size_t)NTOK * DIM];
__device__ __half g_xi[(size_t)NTOK * DINNER];
__device__ __half g_dt[(size_t)NTOK * DTRANK];
__device__ __half g_g[(size_t)NTOK * DINNER];
__device__ float  g_segsum[(size_t)NSEG * BB * DINNER];
__device__ float  g_segc[(size_t)NSEG * BB * DINNER * DSTATE];
// transposed weights [N,K] fp16; x_proj padded to 128 rows (96..127 zero)
__device__ __half g_ipT[(size_t)(2 * DINNER) * DIM];
__device__ __half g_xpT[(size_t)128 * DINNER];
__device__ __half g_dwT[(size_t)DINNER * DTRANK];
__device__ __half g_opT[(size_t)DIM * DINNER];

// ---------------------------------------------------------------------------
// PTX helpers
// ---------------------------------------------------------------------------
__device__ __forceinline__ uint32_t smem_u32(const void* p) {
    uint32_t a;
    asm("{ .reg .u64 t; cvta.to.shared.u64 t, %1; cvt.u32.u64 %0, t; }" : "=r"(a) : "l"(p));
    return a;
}
__device__ __forceinline__ void cp16(uint32_t dst, const void* src) {
    asm volatile("cp.async.cg.shared.global [%0], [%1], 16;" :: "r"(dst), "l"(src));
}
#define CP_COMMIT() asm volatile("cp.async.commit_group;" ::: "memory")
#define CP_WAIT(n)  asm volatile("cp.async.wait_group %0;" :: "n"(n) : "memory")

#define LDSM4(r, a) \
    asm volatile("ldmatrix.sync.aligned.m8n8.x4.shared.b16 {%0,%1,%2,%3}, [%4];" \
        : "=r"((r)[0]), "=r"((r)[1]), "=r"((r)[2]), "=r"((r)[3]) : "r"(a))

#define MMA16816(d, a, b0, b1) \
    asm volatile("mma.sync.aligned.m16n8k16.row.col.f32.f16.f16.f32 " \
        "{%0,%1,%2,%3}, {%4,%5,%6,%7}, {%8,%9}, {%0,%1,%2,%3};" \
        : "+f"((d)[0]), "+f"((d)[1]), "+f"((d)[2]), "+f"((d)[3]) \
        : "r"((a)[0]), "r"((a)[1]), "r"((a)[2]), "r"((a)[3]), "r"(b0), "r"(b1))

// powers P[s] = E^(s+1) via repeated squaring
__device__ __forceinline__ void exp_powers(float E, float* P) {
    float E2 = E * E, E4 = E2 * E2, E8 = E4 * E4;
    P[0]=E;      P[1]=E2;      P[2]=E2*E;     P[3]=E4;
    P[4]=E4*E;   P[5]=E4*E2;   P[6]=E4*P[2];  P[7]=E8;
    P[8]=E8*E;   P[9]=E8*E2;   P[10]=E8*P[2]; P[11]=E8*E4;
    P[12]=E8*P[4]; P[13]=E8*P[5]; P[14]=E8*P[6]; P[15]=E8*E8;
}

// ---------------------------------------------------------------------------
// Fused prep: weight transposes (fp32 [R,C] -> fp16 [C,R]) + rmsnorm, one grid.
// ---------------------------------------------------------------------------
__device__ __forceinline__ void transpose_tile(const float* __restrict__ W,
                                               __half* __restrict__ T,
                                               int R, int C, int cb, int rb) {
    __shared__ float t[32][33];
    const int tx = threadIdx.x & 31, ty = threadIdx.x >> 5;
    int c0 = cb * 32, r0 = rb * 32;
    int c = c0 + tx;
    for (int i = ty; i < 32; i += 8) {
        int r = r0 + i;
        if (r < R && c < C) t[i][tx] = W[(size_t)r * C + c];
    }
    __syncthreads();
    int k = r0 + tx;
    for (int i = ty; i < 32; i += 8) {
        int n = c0 + i;
        if (n < C && k < R)
            T[(size_t)n * R + k] = __float2half(t[tx][i]);
    }
}

__global__ void __launch_bounds__(256)
prep_kernel(const float* __restrict__ in_proj, const float* __restrict__ x_proj,
            const float* __restrict__ dt_w,    const float* __restrict__ out_proj,
            __half* __restrict__ ipT, __half* __restrict__ xpT,
            __half* __restrict__ dwT, __half* __restrict__ opT,
            const float* __restrict__ x, const float* __restrict__ rms_w,
            __half* __restrict__ xn) {
    int bid = blockIdx.x;
    if (bid < 4096) {
        transpose_tile(in_proj, ipT, DIM, 2 * DINNER, bid & 127, bid >> 7);
    } else if (bid < 4288) {
        int i = bid - 4096;
        transpose_tile(x_proj, xpT, DINNER, DBC_W, i % 3, i / 3);
    } else if (bid < 4416) {
        int i = bid - 4288;
        transpose_tile(dt_w, dwT, DTRANK, DINNER, i & 63, i >> 6);
    } else if (bid < 6464) {
        int i = bid - 4416;
        transpose_tile(out_proj, opT, DINNER, DIM, i & 31, i >> 5);
    } else {
        int t = bid - 6464;
        const float* xr = x + (size_t)t * DIM;
        float s = 0.f;
        for (int i = threadIdx.x; i < DIM; i += 256) { float v = xr[i]; s += v * v; }
        #pragma unroll
        for (int off = 16; off > 0; off >>= 1) s += __shfl_xor_sync(0xffffffffu, s, off);
        __shared__ float red[8];
        int wid = threadIdx.x >> 5;
        if ((threadIdx.x & 31) == 0) red[wid] = s;
        __syncthreads();
        __shared__ float sscale;
        if (threadIdx.x == 0) {
            float tot = 0.f;
            #pragma unroll
            for (int i = 0; i < 8; i++) tot += red[i];
            sscale = rsqrtf(tot * (1.0f / DIM) + 1e-5f);
        }
        __syncthreads();
        float scale = sscale;
        for (int i = threadIdx.x * 2; i < DIM; i += 512) {
            float2 v = *(const float2*)(xr + i);
            float2 wv = *(const float2*)(rms_w + i);
            *(__half2*)(xn + (size_t)t * DIM + i) =
                __floats2half2_rn(v.x * scale * wv.x, v.y * scale * wv.y);
        }
    }
}

// ---------------------------------------------------------------------------
// mma.sync fp16 GEMM: C[M,N] = A[M,K] @ B[N,K]^T, fp32 accumulate.
// 128x128x32 tile, 256 threads, 4-stage cp.async pipeline (R10 config).
// MODE 0: fp32 out  1: softplus(+bias) -> fp16  2: +res -> fp32
// MODE 4: fp16 out, silu applied to columns >= DINNER (the z half)
// ---------------------------------------------------------------------------
#define TSB   10240
#define STGB  (2 * TSB)
#define SMEM_GEMM (4 * STGB)          // 81920

template<int MODE>
__global__ void __launch_bounds__(256)
mma_gemm(const __half* __restrict__ A, const __half* __restrict__ B,
         void* __restrict__ Cv, int N, int K, int ld,
         const float* __restrict__ extra, int kpz, size_t czs) {
    extern __shared__ char smem[];
    const uint32_t sb = smem_u32(smem);
    const int tid  = threadIdx.x;
    const int lane = tid & 31;
    const int wid  = tid >> 5;
    const int wm = (wid & 3) * 32;
    const int wn = (wid >> 2) * 64;
    const int row0 = blockIdx.y * 128;
    const int col0 = blockIdx.x * 128;
    const int nch = K >> 5;

    A += (size_t)blockIdx.z * kpz;
    B += (size_t)blockIdx.z * kpz;
    float*  Cf = (float*)Cv + blockIdx.z * czs;
    __half* Ch = (__half*)Cv;

    auto load_stage = [&](int st, int k0) {
        uint32_t base = sb + st * STGB;
        #pragma unroll
        for (int u = 0; u < 2; u++) {
            int i = u * 256 + tid;
            int r = i >> 2, seg = i & 3;
            uint32_t d = base + r * 80 + seg * 16;
            cp16(d,       A + (size_t)(row0 + r) * ld + k0 + seg * 8);
            cp16(d + TSB, B + (size_t)(col0 + r) * ld + k0 + seg * 8);
        }
    };

    float acc[2][8][4];
    #pragma unroll
    for (int mi = 0; mi < 2; mi++)
        #pragma unroll
        for (int ni = 0; ni < 8; ni++)
            #pragma unroll
            for (int q = 0; q < 4; q++) acc[mi][ni][q] = 0.f;

    const int lrow = lane & 15;
    const int lkb  = lane >> 4;

    load_stage(0, 0);                      CP_COMMIT();
    if (nch > 1) load_stage(1, 32);        CP_COMMIT();
    if (nch > 2) load_stage(2, 64);        CP_COMMIT();

    for (int kc = 0; kc < nch; kc++) {
        CP_WAIT(2);
        __syncthreads();
        if (kc + 3 < nch) load_stage((kc + 3) & 3, (kc + 3) << 5);
        CP_COMMIT();

        uint32_t base = sb + (kc & 3) * STGB;
        #pragma unroll
        for (int ks = 0; ks < 2; ks++) {
            uint32_t koff = (ks * 16 + lkb * 8) * 2;
            uint32_t ah[2][4];
            #pragma unroll
            for (int mi = 0; mi < 2; mi++)
                LDSM4(ah[mi], base + (wm + mi * 16 + lrow) * 80 + koff);
            uint32_t bf[4][4];
            #pragma unroll
            for (int p = 0; p < 4; p++)
                LDSM4(bf[p], base + TSB + (wn + p * 16 + lrow) * 80 + koff);
            #pragma unroll
            for (int mi = 0; mi < 2; mi++)
                #pragma unroll
                for (int p = 0; p < 4; p++)
                    #pragma unroll
                    for (int hb = 0; hb < 2; hb++)
                        MMA16816(acc[mi][p * 2 + hb], ah[mi], bf[p][hb], bf[p][hb + 2]);
        }
        __syncthreads();
    }

    const int rb = row0 + wm + (lane >> 2);
    const int cb = col0 + wn + (lane & 3) * 2;
    #pragma unroll
    for (int mi = 0; mi < 2; mi++)
        #pragma unroll
        for (int ni = 0; ni < 8; ni++) {
            int c = cb + ni * 8;
            if (c >= N) continue;
            #pragma unroll
            for (int half = 0; half < 2; half++) {
                int r = rb + mi * 16 + half * 8;
                float v0 = acc[mi][ni][half * 2 + 0];
                float v1 = acc[mi][ni][half * 2 + 1];
                if (MODE == 1) {
                    v0 += extra[c];     v1 += extra[c + 1];
                    v0 = (v0 > 20.f) ? v0 : log1pf(__expf(v0));
                    v1 = (v1 > 20.f) ? v1 : log1pf(__expf(v1));
                } else if (MODE == 2) {
                    const float2 res = *(const float2*)(extra + (size_t)r * N + c);
                    v0 += res.x; v1 += res.y;
                } else if (MODE == 4) {
                    if (c >= DINNER) {   // z half -> store silu(z)
                        v0 = v0 / (1.f + __expf(-v0));
                        v1 = v1 / (1.f + __expf(-v1));
                    }
                }
                if (MODE == 0 || MODE == 2)
                    *(float2*)(Cf + (size_t)r * N + c) = make_float2(v0, v1);
                else
                    *(__half2*)(Ch + (size_t)r * N + c) = __floats2half2_rn(v0, v1);
            }
        }
}

// ---------------------------------------------------------------------------
// Split-K reduce for dbc + dt fp16
// ---------------------------------------------------------------------------
__global__ void reduce_dbc(const float* __restrict__ part,
                           float* __restrict__ dbc,
                           __half* __restrict__ dt) {
    int i = blockIdx.x * blockDim.x + threadIdx.x;
    int r = i >> 7, c = i & 127;
    float s = 0.f;
    #pragma unroll
    for (int p = 0; p < KSPLIT; p++)
        s += part[(size_t)p * NTOK * 128 + i];
    if (c < DBC_W) dbc[(size_t)r * DBC_W + c] = s;
    if (c < DTRANK) dt[(size_t)r * DTRANK + c] = __float2half(s);
}

// ---------------------------------------------------------------------------
// Causal depthwise conv (K=4) + bias + SiLU: fp16 xz -> fp16 xi, 4 ch/thread
// ---------------------------------------------------------------------------
__global__ void conv_silu_kernel(const __half* __restrict__ xz,
                                 const float* __restrict__ conv_w,
                                 const float* __restrict__ conv_b,
                                 __half* __restrict__ xi) {
    size_t i4 = (size_t)blockIdx.x * blockDim.x + threadIdx.x;
    size_t idx = i4 * 4;
    if (idx >= (size_t)NTOK * DINNER) return;
    int c = (int)(idx % DINNER);
    int t = (int)(idx / DINNER);
    int l = t % LL;
    int tb = t - l;
    float4 acc = *(const float4*)(conv_b + c);
    const float4 w0 = *(const float4*)(conv_w + (c + 0) * DCONV);
    const float4 w1 = *(const float4*)(conv_w + (c + 1) * DCONV);
    const float4 w2 = *(const float4*)(conv_w + (c + 2) * DCONV);
    const float4 w3 = *(const float4*)(conv_w + (c + 3) * DCONV);
    const float wk[4][4] = {{w0.x, w0.y, w0.z, w0.w}, {w1.x, w1.y, w1.z, w1.w},
                            {w2.x, w2.y, w2.z, w2.w}, {w3.x, w3.y, w3.z, w3.w}};
    #pragma unroll
    for (int k = 0; k < DCONV; k++) {
        int ls = l - (DCONV - 1) + k;
        if (ls >= 0) {
            uint2 p = *(const uint2*)(xz + (size_t)(tb + ls) * (2 * DINNER) + c);
            __half2 v01 = *(__half2*)&p.x;
            __half2 v23 = *(__half2*)&p.y;
            acc.x += __half2float(__low2half(v01))  * wk[0][k];
            acc.y += __half2float(__high2half(v01)) * wk[1][k];
            acc.z += __half2float(__low2half(v23))  * wk[2][k];
            acc.w += __half2float(__high2half(v23)) * wk[3][k];
        }
    }
    float s0 = acc.x / (1.f + __expf(-acc.x));
    float s1 = acc.y / (1.f + __expf(-acc.y));
    float s2 = acc.z / (1.f + __expf(-acc.z));
    float s3 = acc.w / (1.f + __expf(-acc.w));
    __half2 h01 = __floats2half2_rn(s0, s1);
    __half2 h23 = __floats2half2_rn(s2, s3);
    uint2 pack;
    pack.x = *(uint32_t*)&h01;
    pack.y = *(uint32_t*)&h23;
    *(uint2*)(xi + idx) = pack;
}

// ---------------------------------------------------------------------------
// Scan pass 1 (128 threads = 128 channels/block): segment transfer
//   sd = sum(delta), cvec[s] = recurrence from h=0 over SEGLEN steps.
// ---------------------------------------------------------------------------
#define SCHUNK 16
#define SSTG1  9216                    // delta 4K | xi 4K | B 1K
__global__ __launch_bounds__(128, 1)
void scan_pass1(const float* __restrict__ dbc,
                const __half* __restrict__ delta,
                const __half* __restrict__ xi,
                const float* __restrict__ A_log,
                float* __restrict__ segsum,
                float* __restrict__ segc) {
    __shared__ char sbuf[4 * SSTG1];
    const uint32_t sb = smem_u32(sbuf);
    const int seg   = blockIdx.y;
    const int b     = blockIdx.x >> 4;
    const int cbase = (blockIdx.x & 15) * 128;
    const int tid   = threadIdx.x;
    const int c     = cbase + tid;
    const size_t tok0 = (size_t)b * LL + (size_t)seg * SEGLEN;

    float A[DSTATE];
    #pragma unroll
    for (int s = 0; s < DSTATE; s++) A[s] = -__expf(A_log[c * DSTATE + s]);
    const float a1 = A[0];
    bool pat = true;
    #pragma unroll
    for (int s = 0; s < DSTATE; s++)
        pat = pat && (fabsf(A[s] - (float)(s + 1) * a1) <= 1e-5f * fabsf(A[s]));

    float h[DSTATE];
    #pragma unroll
    for (int s = 0; s < DSTATE; s++) h[s] = 0.f;
    float sd = 0.f;

    auto stage_load = [&](int st, int l0) {
        uint32_t base = sb + st * SSTG1;
        #pragma unroll
        for (int u0 = 0; u0 < 5; u0++) {
            int u = u0 * 128 + tid;
            if (u >= 576) break;
            uint32_t dst; const void* src;
            if (u < 256) {               // delta fp16 [16][128]
                int r = u >> 4, s = u & 15;
                dst = base + r * 256 + s * 16;
                src = delta + (tok0 + l0 + r) * DINNER + cbase + s * 8;
            } else if (u < 512) {        // xi fp16 [16][128]
                int v = u - 256; int r = v >> 4, s = v & 15;
                dst = base + 4096 + r * 256 + s * 16;
                src = xi + (tok0 + l0 + r) * DINNER + cbase + s * 8;
            } else {                     // B fp32 [16][16]
                int v = u - 512; int r = v >> 2, s = v & 3;
                dst = base + 8192 + r * 64 + s * 16;
                src = dbc + (tok0 + l0 + r) * DBC_W + DTRANK + s * 4;
            }
            cp16(dst, src);
        }
    };

    const int nch = SEGLEN / SCHUNK;   // 16
    stage_load(0, 0);          CP_COMMIT();
    stage_load(1, SCHUNK);     CP_COMMIT();
    stage_load(2, 2 * SCHUNK); CP_COMMIT();

    for (int ck = 0; ck < nch; ck++) {
        CP_WAIT(2);
        __syncthreads();
        if (ck + 3 < nch) stage_load((ck + 3) & 3, (ck + 3) * SCHUNK);
        CP_COMMIT();

        const char* base = sbuf + (ck & 3) * SSTG1;
        const __half* sd16 = (const __half*)(base);
        const __half* sxi  = (const __half*)(base + 4096);
        const float*  sB   = (const float*)(base + 8192);

        #pragma unroll 4
        for (int l = 0; l < SCHUNK; l++) {
            float d  = __half2float(sd16[l * 128 + tid]);
            float xv = __half2float(sxi[l * 128 + tid]);
            const float* Bv = sB + l * 16;
            float dx = d * xv;
            if (pat) {
                float P[DSTATE];
                exp_powers(__expf(d * a1), P);
                #pragma unroll
                for (int s = 0; s < DSTATE; s++)
                    h[s] = P[s] * h[s] + dx * Bv[s];
            } else {
                #pragma unroll
                for (int s = 0; s < DSTATE; s++)
                    h[s] = __expf(d * A[s]) * h[s] + dx * Bv[s];
            }
            sd += d;
        }
        __syncthreads();
    }

    size_t bc = (size_t)seg * BB * DINNER + (size_t)b * DINNER + c;
    segsum[bc] = sd;
    #pragma unroll
    for (int s = 0; s < DSTATE; s++)
        segc[bc * DSTATE + s] = h[s];
}

// ---------------------------------------------------------------------------
// Scan pass 2 (128 threads): fold prefix segments, run SEGLEN steps emitting
// gated output.  z half of xz already holds silu(z).
// ---------------------------------------------------------------------------
#define SSTG2  14336                   // delta 4K | sz 4K | xi 4K | bc 2K
__global__ __launch_bounds__(128, 1)
void scan_pass2(const float* __restrict__ dbc,
                const __half* __restrict__ delta,
                const __half* __restrict__ xi,
                const __half* __restrict__ xz,
                const float* __restrict__ A_log,
                const float* __restrict__ Dp,
                const float* __restrict__ segsum,
                const float* __restrict__ segc,
                __half* __restrict__ gout) {
    __shared__ char sbuf[4 * SSTG2];
    const uint32_t sb = smem_u32(sbuf);
    const int seg   = blockIdx.y;
    const int b     = blockIdx.x >> 4;
    const int cbase = (blockIdx.x & 15) * 128;
    const int tid   = threadIdx.x;
    const int c     = cbase + tid;
    const size_t tok0 = (size_t)b * LL + (size_t)seg * SEGLEN;

    float A[DSTATE];
    #pragma unroll
    for (int s = 0; s < DSTATE; s++) A[s] = -__expf(A_log[c * DSTATE + s]);
    const float a1 = A[0];
    bool pat = true;
    #pragma unroll
    for (int s = 0; s < DSTATE; s++)
        pat = pat && (fabsf(A[s] - (float)(s + 1) * a1) <= 1e-5f * fabsf(A[s]));
    const float Dv = Dp[c];

    float h[DSTATE];
    #pragma unroll
    for (int s = 0; s < DSTATE; s++) h[s] = 0.f;
    for (int j = 0; j < seg; j++) {
        size_t bc = (size_t)j * BB * DINNER + (size_t)b * DINNER + c;
        float sdj = segsum[bc];
        if (pat) {
            float P[DSTATE];
            exp_powers(__expf(sdj * a1), P);
            #pragma unroll
            for (int s = 0; s < DSTATE; s++)
                h[s] = P[s] * h[s] + segc[bc * DSTATE + s];
        } else {
            #pragma unroll
            for (int s = 0; s < DSTATE; s++)
                h[s] = __expf(sdj * A[s]) * h[s] + segc[bc * DSTATE + s];
        }
    }

    auto stage_load = [&](int st, int l0) {
        uint32_t base = sb + st * SSTG2;
        #pragma unroll
        for (int u0 = 0; u0 < 7; u0++) {
            int u = u0 * 128 + tid;
            if (u >= 896) break;
            uint32_t dst; const void* src;
            if (u < 256) {               // delta fp16 [16][128]
                int r = u >> 4, s = u & 15;
                dst = base + r * 256 + s * 16;
                src = delta + (tok0 + l0 + r) * DINNER + cbase + s * 8;
            } else if (u < 512) {        // silu(z) fp16
                int v = u - 256; int r = v >> 4, s = v & 15;
                dst = base + 4096 + r * 256 + s * 16;
                src = xz + (tok0 + l0 + r) * (2 * DINNER) + DINNER + cbase + s * 8;
            } else if (u < 768) {        // xi fp16
                int v = u - 512; int r = v >> 4, s = v & 15;
                dst = base + 8192 + r * 256 + s * 16;
                src = xi + (tok0 + l0 + r) * DINNER + cbase + s * 8;
            } else {                     // bc fp32 [16][32]
                int v = u - 768; int r = v >> 3, s = v & 7;
                dst = base + 12288 + r * 128 + s * 16;
                src = dbc + (tok0 + l0 + r) * DBC_W + DTRANK + s * 4;
            }
            cp16(dst, src);
        }
    };

    const int nch = SEGLEN / SCHUNK;   // 16
    stage_load(0, 0);          CP_COMMIT();
    stage_load(1, SCHUNK);     CP_COMMIT();
    stage_load(2, 2 * SCHUNK); CP_COMMIT();

    for (int ck = 0; ck < nch; ck++) {
        CP_WAIT(2);
        __syncthreads();
        if (ck + 3 < nch) stage_load((ck + 3) & 3, (ck + 3) * SCHUNK);
        CP_COMMIT();

        const char* base = sbuf + (ck & 3) * SSTG2;
        const __half* sd16 = (const __half*)(base);
        const __half* ssg  = (const __half*)(base + 4096);
        const __half* sxi  = (const __half*)(base + 8192);
        const float*  sbc  = (const float*)(base + 12288);
        const int l0 = ck * SCHUNK;

        #pragma unroll 4
        for (int l = 0; l < SCHUNK; l++) {
            float d  = __half2float(sd16[l * 128 + tid]);
            float sg = __half2float(ssg[l * 128 + tid]);   // already silu(z)
            float xv = __half2float(sxi[l * 128 + tid]);
            const float* Bv = sbc + l * 32;
            const float* Cv = Bv + DSTATE;
            float dx = d * xv;
            float y = 0.f;
            if (pat) {
                float P[DSTATE];
                exp_powers(__expf(d * a1), P);
                #pragma unroll
                for (int s = 0; s < DSTATE; s++) {
                    h[s] = P[s] * h[s] + dx * Bv[s];
                    y = fmaf(h[s], Cv[s], y);
                }
            } else {
                #pragma unroll
                for (int s = 0; s < DSTATE; s++) {
                    h[s] = __expf(d * A[s]) * h[s] + dx * Bv[s];
                    y = fmaf(h[s], Cv[s], y);
                }
            }
            float g = y + xv * Dv;
            gout[(tok0 + l0 + l) * DINNER + c] = __float2half(g * sg);
        }
        __syncthreads();
    }
}

// ---------------------------------------------------------------------------
// Launch
// ---------------------------------------------------------------------------
extern "C" void kernel_launch(void* const* d_in, const int* in_sizes, int n_in,
                              void* d_out, int out_size) {
    const float* x        = (const float*)d_in[0];
    const float* rms_w    = (const float*)d_in[1];
    const float* in_proj  = (const float*)d_in[2];
    const float* conv_w   = (const float*)d_in[3];
    const float* conv_b   = (const float*)d_in[4];
    const float* x_proj   = (const float*)d_in[5];
    const float* dt_w     = (const float*)d_in[6];
    const float* dt_b     = (const float*)d_in[7];
    const float* A_log    = (const float*)d_in[8];
    const float* Dp       = (const float*)d_in[9];
    const float* out_proj = (const float*)d_in[10];
    float* out = (float*)d_out;

    float *dbc, *dbcp, *segsum, *segc;
    __half *xz, *delta, *xn, *xi, *dt, *gg, *ipT, *xpT, *dwT, *opT;
    cudaGetSymbolAddress((void**)&xz,     g_xz);
    cudaGetSymbolAddress((void**)&dbc,    g_dbc);
    cudaGetSymbolAddress((void**)&dbcp,   g_dbcp);
    cudaGetSymbolAddress((void**)&delta,  g_delta);
    cudaGetSymbolAddress((void**)&xn,     g_xn);
    cudaGetSymbolAddress((void**)&xi,     g_xi);
    cudaGetSymbolAddress((void**)&dt,     g_dt);
    cudaGetSymbolAddress((void**)&gg,     g_g);
    cudaGetSymbolAddress((void**)&segsum, g_segsum);
    cudaGetSymbolAddress((void**)&segc,   g_segc);
    cudaGetSymbolAddress((void**)&ipT,    g_ipT);
    cudaGetSymbolAddress((void**)&xpT,    g_xpT);
    cudaGetSymbolAddress((void**)&dwT,    g_dwT);
    cudaGetSymbolAddress((void**)&opT,    g_opT);

    cudaFuncSetAttribute(mma_gemm<0>, cudaFuncAttributeMaxDynamicSharedMemorySize, SMEM_GEMM);
    cudaFuncSetAttribute(mma_gemm<1>, cudaFuncAttributeMaxDynamicSharedMemorySize, SMEM_GEMM);
    cudaFuncSetAttribute(mma_gemm<2>, cudaFuncAttributeMaxDynamicSharedMemorySize, SMEM_GEMM);
    cudaFuncSetAttribute(mma_gemm<4>, cudaFuncAttributeMaxDynamicSharedMemorySize, SMEM_GEMM);

    // 0+1. fused prep: 4 weight transposes + rmsnorm in ONE launch
    prep_kernel<<<6464 + NTOK, 256>>>(in_proj, x_proj, dt_w, out_proj,
                                      ipT, xpT, dwT, opT, x, rms_w, xn);

    // 2. xz = xn @ in_proj -> fp16 (z half stored as silu(z))
    {
        dim3 grid(2 * DINNER / 128, NTOK / 128);
        mma_gemm<4><<<grid, 256, SMEM_GEMM>>>(xn, ipT, xz, 2 * DINNER, DIM, DIM,
                                              nullptr, 0, 0);
    }

    // 3. conv + silu -> xi fp16
    {
        size_t n4 = (size_t)NTOK * DINNER / 4;
        conv_silu_kernel<<<(unsigned)((n4 + 255) / 256), 256>>>(xz, conv_w, conv_b, xi);
    }

    // 4. dbc = xi @ x_proj: split-K x4 in ONE launch (gridDim.z) + reduce
    {
        const int kpart = DINNER / KSPLIT;   // 512
        dim3 grid(1, NTOK / 128, KSPLIT);
        mma_gemm<0><<<grid, 256, SMEM_GEMM>>>(xi, xpT, dbcp, 128, kpart, DINNER,
                                              nullptr, kpart, (size_t)NTOK * 128);
        reduce_dbc<<<NTOK * 128 / 256, 256>>>(dbcp, dbc, dt);
    }

    // 5. delta = softplus(dt @ dt_w + dt_b) -> fp16  [8192 x 2048], K=64
    {
        dim3 grid(DINNER / 128, NTOK / 128);
        mma_gemm<1><<<grid, 256, SMEM_GEMM>>>(dt, dwT, delta, DINNER, DTRANK, DTRANK,
                                              dt_b, 0, 0);
    }

    // 6. parallel selective scan (2 passes, 128-thread blocks)
    {
        dim3 g1(BB * (DINNER / 128), NSEG - 1);
        scan_pass1<<<g1, 128>>>(dbc, delta, xi, A_log, segsum, segc);
        dim3 g2(BB * (DINNER / 128), NSEG);
        scan_pass2<<<g2, 128>>>(dbc, delta, xi, xz, A_log, Dp, segsum, segc, gg);
    }

    // 7. out = x + gated @ out_proj  [8192 x 1024], K=2048
    {
        dim3 grid(DIM / 128, NTOK / 128);
        mma_gemm<2><<<grid, 256, SMEM_GEMM>>>(gg, opT, out, DIM, DINNER, DINNER,
                                              x, 0, 0);
    }
}

// round 13
// speedup vs baseline: 1.0635x; 1.0123x over previous
#include <cuda_runtime.h>
#include <cuda_fp16.h>
#include <math.h>
#include <stdint.h>

// ---------------------------------------------------------------------------
// Mamba block: B=4, L=2048, dim=1024, d_inner=2048, d_state=16, K=4, dt_rank=64
// Baseline sm_103 PTX -> ldmatrix + mma.sync fp16 HMMA (fp32 accum).
// fp16 operands + fp16 intermediates; err ~1e-4 < 1e-3 gate.
// System is effective-BW bound (~2 TB/s): optimize by CUTTING BYTES.
// R13: conv+silu fused into GEMM2's A-load (xi produced as byproduct);
//      conv kernel deleted (-64 MB traffic, -1 launch).
// ---------------------------------------------------------------------------
#define BB      4
#define LL      2048
#define DIM     1024
#define DINNER  2048
#define DSTATE  16
#define DCONV   4
#define DTRANK  64
#define NTOK    (BB * LL)              // 8192
#define DBC_W   (DTRANK + 2 * DSTATE)  // 96
#define KSPLIT  4
#define NSEG    8
#define SEGLEN  (LL / NSEG)            // 256

// ---------------------------------------------------------------------------
// Scratch (device globals; zero-initialized)
// ---------------------------------------------------------------------------
__device__ __half g_xz[(size_t)NTOK * 2 * DINNER];       // z half stores silu(z)
__device__ float  g_dbc[(size_t)NTOK * DBC_W];
__device__ float  g_dbcp[(size_t)KSPLIT * NTOK * 128];
__device__ __half g_delta[(size_t)NTOK * DINNER];
__device__ __half g_xn[(size_t)NTOK * DIM];
__device__ __half g_xi[(size_t)NTOK * DINNER];
__device__ __half g_dt[(size_t)NTOK * DTRANK];
__device__ __half g_g[(size_t)NTOK * DINNER];
__device__ float  g_segsum[(size_t)NSEG * BB * DINNER];
__device__ float  g_segc[(size_t)NSEG * BB * DINNER * DSTATE];
// transposed weights [N,K] fp16; x_proj padded to 128 rows (96..127 zero)
__device__ __half g_ipT[(size_t)(2 * DINNER) * DIM];
__device__ __half g_xpT[(size_t)128 * DINNER];
__device__ __half g_dwT[(size_t)DINNER * DTRANK];
__device__ __half g_opT[(size_t)DIM * DINNER];

// ---------------------------------------------------------------------------
// PTX helpers
// ---------------------------------------------------------------------------
__device__ __forceinline__ uint32_t smem_u32(const void* p) {
    uint32_t a;
    asm("{ .reg .u64 t; cvta.to.shared.u64 t, %1; cvt.u32.u64 %0, t; }" : "=r"(a) : "l"(p));
    return a;
}
__device__ __forceinline__ void cp16(uint32_t dst, const void* src) {
    asm volatile("cp.async.cg.shared.global [%0], [%1], 16;" :: "r"(dst), "l"(src));
}
#define CP_COMMIT() asm volatile("cp.async.commit_group;" ::: "memory")
#define CP_WAIT(n)  asm volatile("cp.async.wait_group %0;" :: "n"(n) : "memory")

#define LDSM4(r, a) \
    asm volatile("ldmatrix.sync.aligned.m8n8.x4.shared.b16 {%0,%1,%2,%3}, [%4];" \
        : "=r"((r)[0]), "=r"((r)[1]), "=r"((r)[2]), "=r"((r)[3]) : "r"(a))

#define MMA16816(d, a, b0, b1) \
    asm volatile("mma.sync.aligned.m16n8k16.row.col.f32.f16.f16.f32 " \
        "{%0,%1,%2,%3}, {%4,%5,%6,%7}, {%8,%9}, {%0,%1,%2,%3};" \
        : "+f"((d)[0]), "+f"((d)[1]), "+f"((d)[2]), "+f"((d)[3]) \
        : "r"((a)[0]), "r"((a)[1]), "r"((a)[2]), "r"((a)[3]), "r"(b0), "r"(b1))

// powers P[s] = E^(s+1) via repeated squaring
__device__ __forceinline__ void exp_powers(float E, float* P) {
    float E2 = E * E, E4 = E2 * E2, E8 = E4 * E4;
    P[0]=E;      P[1]=E2;      P[2]=E2*E;     P[3]=E4;
    P[4]=E4*E;   P[5]=E4*E2;   P[6]=E4*P[2];  P[7]=E8;
    P[8]=E8*E;   P[9]=E8*E2;   P[10]=E8*P[2]; P[11]=E8*E4;
    P[12]=E8*P[4]; P[13]=E8*P[5]; P[14]=E8*P[6]; P[15]=E8*E8;
}

// ---------------------------------------------------------------------------
// Fused prep: weight transposes (fp32 [R,C] -> fp16 [C,R]) + rmsnorm, one grid.
// ---------------------------------------------------------------------------
__device__ __forceinline__ void transpose_tile(const float* __restrict__ W,
                                               __half* __restrict__ T,
                                               int R, int C, int cb, int rb) {
    __shared__ float t[32][33];
    const int tx = threadIdx.x & 31, ty = threadIdx.x >> 5;
    int c0 = cb * 32, r0 = rb * 32;
    int c = c0 + tx;
    for (int i = ty; i < 32; i += 8) {
        int r = r0 + i;
        if (r < R && c < C) t[i][tx] = W[(size_t)r * C + c];
    }
    __syncthreads();
    int k = r0 + tx;
    for (int i = ty; i < 32; i += 8) {
        int n = c0 + i;
        if (n < C && k < R)
            T[(size_t)n * R + k] = __float2half(t[tx][i]);
    }
}

__global__ void __launch_bounds__(256)
prep_kernel(const float* __restrict__ in_proj, const float* __restrict__ x_proj,
            const float* __restrict__ dt_w,    const float* __restrict__ out_proj,
            __half* __restrict__ ipT, __half* __restrict__ xpT,
            __half* __restrict__ dwT, __half* __restrict__ opT,
            const float* __restrict__ x, const float* __restrict__ rms_w,
            __half* __restrict__ xn) {
    int bid = blockIdx.x;
    if (bid < 4096) {
        transpose_tile(in_proj, ipT, DIM, 2 * DINNER, bid & 127, bid >> 7);
    } else if (bid < 4288) {
        int i = bid - 4096;
        transpose_tile(x_proj, xpT, DINNER, DBC_W, i % 3, i / 3);
    } else if (bid < 4416) {
        int i = bid - 4288;
        transpose_tile(dt_w, dwT, DTRANK, DINNER, i & 63, i >> 6);
    } else if (bid < 6464) {
        int i = bid - 4416;
        transpose_tile(out_proj, opT, DINNER, DIM, i & 31, i >> 5);
    } else {
        int t = bid - 6464;
        const float* xr = x + (size_t)t * DIM;
        float s = 0.f;
        for (int i = threadIdx.x; i < DIM; i += 256) { float v = xr[i]; s += v * v; }
        #pragma unroll
        for (int off = 16; off > 0; off >>= 1) s += __shfl_xor_sync(0xffffffffu, s, off);
        __shared__ float red[8];
        int wid = threadIdx.x >> 5;
        if ((threadIdx.x & 31) == 0) red[wid] = s;
        __syncthreads();
        __shared__ float sscale;
        if (threadIdx.x == 0) {
            float tot = 0.f;
            #pragma unroll
            for (int i = 0; i < 8; i++) tot += red[i];
            sscale = rsqrtf(tot * (1.0f / DIM) + 1e-5f);
        }
        __syncthreads();
        float scale = sscale;
        for (int i = threadIdx.x * 2; i < DIM; i += 512) {
            float2 v = *(const float2*)(xr + i);
            float2 wv = *(const float2*)(rms_w + i);
            *(__half2*)(xn + (size_t)t * DIM + i) =
                __floats2half2_rn(v.x * scale * wv.x, v.y * scale * wv.y);
        }
    }
}

// ---------------------------------------------------------------------------
// mma.sync fp16 GEMM: C[M,N] = A[M,K] @ B[N,K]^T, fp32 accumulate.
// 128x128x32 tile, 256 threads, 4-stage cp.async (R10/R12 proven config).
// MODE 1: softplus(+bias) -> fp16  2: +res -> fp32
// MODE 4: fp16 out, silu applied to columns >= DINNER (the z half)
// ---------------------------------------------------------------------------
#define TSB   10240
#define STGB  (2 * TSB)
#define SMEM_GEMM (4 * STGB)          // 81920

template<int MODE>
__global__ void __launch_bounds__(256)
mma_gemm(const __half* __restrict__ A, const __half* __restrict__ B,
         void* __restrict__ Cv, int N, int K, int ld,
         const float* __restrict__ extra) {
    extern __shared__ char smem[];
    const uint32_t sb = smem_u32(smem);
    const int tid  = threadIdx.x;
    const int lane = tid & 31;
    const int wid  = tid >> 5;
    const int wm = (wid & 3) * 32;
    const int wn = (wid >> 2) * 64;
    const int row0 = blockIdx.y * 128;
    const int col0 = blockIdx.x * 128;
    const int nch = K >> 5;

    float*  Cf = (float*)Cv;
    __half* Ch = (__half*)Cv;

    auto load_stage = [&](int st, int k0) {
        uint32_t base = sb + st * STGB;
        #pragma unroll
        for (int u = 0; u < 2; u++) {
            int i = u * 256 + tid;
            int r = i >> 2, seg = i & 3;
            uint32_t d = base + r * 80 + seg * 16;
            cp16(d,       A + (size_t)(row0 + r) * ld + k0 + seg * 8);
            cp16(d + TSB, B + (size_t)(col0 + r) * ld + k0 + seg * 8);
        }
    };

    float acc[2][8][4];
    #pragma unroll
    for (int mi = 0; mi < 2; mi++)
        #pragma unroll
        for (int ni = 0; ni < 8; ni++)
            #pragma unroll
            for (int q = 0; q < 4; q++) acc[mi][ni][q] = 0.f;

    const int lrow = lane & 15;
    const int lkb  = lane >> 4;

    load_stage(0, 0);                      CP_COMMIT();
    if (nch > 1) load_stage(1, 32);        CP_COMMIT();
    if (nch > 2) load_stage(2, 64);        CP_COMMIT();

    for (int kc = 0; kc < nch; kc++) {
        CP_WAIT(2);
        __syncthreads();
        if (kc + 3 < nch) load_stage((kc + 3) & 3, (kc + 3) << 5);
        CP_COMMIT();

        uint32_t base = sb + (kc & 3) * STGB;
        #pragma unroll
        for (int ks = 0; ks < 2; ks++) {
            uint32_t koff = (ks * 16 + lkb * 8) * 2;
            uint32_t ah[2][4];
            #pragma unroll
            for (int mi = 0; mi < 2; mi++)
                LDSM4(ah[mi], base + (wm + mi * 16 + lrow) * 80 + koff);
            uint32_t bf[4][4];
            #pragma unroll
            for (int p = 0; p < 4; p++)
                LDSM4(bf[p], base + TSB + (wn + p * 16 + lrow) * 80 + koff);
            #pragma unroll
            for (int mi = 0; mi < 2; mi++)
                #pragma unroll
                for (int p = 0; p < 4; p++)
                    #pragma unroll
                    for (int hb = 0; hb < 2; hb++)
                        MMA16816(acc[mi][p * 2 + hb], ah[mi], bf[p][hb], bf[p][hb + 2]);
        }
        __syncthreads();
    }

    const int rb = row0 + wm + (lane >> 2);
    const int cb = col0 + wn + (lane & 3) * 2;
    #pragma unroll
    for (int mi = 0; mi < 2; mi++)
        #pragma unroll
        for (int ni = 0; ni < 8; ni++) {
            int c = cb + ni * 8;
            if (c >= N) continue;
            #pragma unroll
            for (int half = 0; half < 2; half++) {
                int r = rb + mi * 16 + half * 8;
                float v0 = acc[mi][ni][half * 2 + 0];
                float v1 = acc[mi][ni][half * 2 + 1];
                if (MODE == 1) {
                    v0 += extra[c];     v1 += extra[c + 1];
                    v0 = (v0 > 20.f) ? v0 : log1pf(__expf(v0));
                    v1 = (v1 > 20.f) ? v1 : log1pf(__expf(v1));
                } else if (MODE == 2) {
                    const float2 res = *(const float2*)(extra + (size_t)r * N + c);
                    v0 += res.x; v1 += res.y;
                } else if (MODE == 4) {
                    if (c >= DINNER) {   // z half -> store silu(z)
                        v0 = v0 / (1.f + __expf(-v0));
                        v1 = v1 / (1.f + __expf(-v1));
                    }
                }
                if (MODE == 2)
                    *(float2*)(Cf + (size_t)r * N + c) = make_float2(v0, v1);
                else
                    *(__half2*)(Ch + (size_t)r * N + c) = __floats2half2_rn(v0, v1);
            }
        }
}

// ---------------------------------------------------------------------------
// GEMM2 fused: dbc partials = conv_silu(xz_x) @ xpT^T, AND writes xi.
// grid (1, NTOK/128, KSPLIT).  A tile computed on the fly from raw xz:
// load [131][32ch] raw slice (3-token halo) + B tile; convert conv+bias+silu
// into the fp16 mma tile; store xi to global (each element exactly once).
// ---------------------------------------------------------------------------
#define RAWA  8384                    // 131 rows x 64 B
#define RSTG  (RAWA + TSB)            // 18624 per stage (rawA + B)
#define AMMA_OFF (4 * RSTG)           // 74496
#define SMEM_G2  (AMMA_OFF + TSB)     // 84736

__global__ void __launch_bounds__(256)
gemm2_fused(const __half* __restrict__ xz,
            const __half* __restrict__ xpT,
            const float* __restrict__ conv_w,
            const float* __restrict__ conv_b,
            __half* __restrict__ xi,
            float* __restrict__ dbcp) {
    extern __shared__ char smem[];
    const uint32_t sb = smem_u32(smem);
    const int tid  = threadIdx.x;
    const int lane = tid & 31;
    const int wid  = tid >> 5;
    const int wm = (wid & 3) * 32;
    const int wn = (wid >> 2) * 64;
    const int row0 = blockIdx.y * 128;              // token base
    const int cz   = blockIdx.z * (DINNER / KSPLIT); // channel base (512/z)
    const bool first = (row0 & (LL - 1)) == 0;       // batch start (halo invalid)
    const int nch = (DINNER / KSPLIT) >> 5;          // 16

    float* Cf = dbcp + (size_t)blockIdx.z * NTOK * 128;

    auto load_stage = [&](int st, int k0) {
        uint32_t base = sb + st * RSTG;
        #pragma unroll
        for (int u0 = 0; u0 < 5; u0++) {
            int u = u0 * 256 + tid;
            if (u >= 1036) break;
            if (u < 524) {                       // raw xz x-half, rows -3..127
                int r = u >> 2, seg = u & 3;
                uint32_t d = base + r * 64 + seg * 16;
                if (first && r < 3) {
                    *(uint4*)(smem + (d - sb)) = make_uint4(0, 0, 0, 0);
                } else {
                    cp16(d, xz + (size_t)(row0 - 3 + r) * (2 * DINNER) + cz + k0 + seg * 8);
                }
            } else {                             // B tile [128][40]
                int v = u - 524;
                int r = v >> 2, seg = v & 3;
                cp16(base + RAWA + r * 80 + seg * 16,
                     xpT + (size_t)r * DINNER + cz + k0 + seg * 8);
            }
        }
    };

    float acc[2][8][4];
    #pragma unroll
    for (int mi = 0; mi < 2; mi++)
        #pragma unroll
        for (int ni = 0; ni < 8; ni++)
            #pragma unroll
            for (int q = 0; q < 4; q++) acc[mi][ni][q] = 0.f;

    const int lrow = lane & 15;
    const int lkb  = lane >> 4;
    const int cch  = tid & 31;        // channel within chunk (convert role)
    const int cg   = tid >> 5;        // token group 0..7

    load_stage(0, 0);   CP_COMMIT();
    load_stage(1, 32);  CP_COMMIT();
    load_stage(2, 64);  CP_COMMIT();

    for (int kc = 0; kc < nch; kc++) {
        CP_WAIT(2);
        __syncthreads();               // stage kc landed; Amma free (LDSM done)
        if (kc + 3 < nch) load_stage((kc + 3) & 3, (kc + 3) << 5);
        CP_COMMIT();

        const int k0 = kc << 5;
        uint32_t rawb = sb + (kc & 3) * RSTG;

        // ---- convert: conv(K=4)+bias+silu -> Amma tile + global xi ----
        {
            const int c = cz + k0 + cch;
            const float4 cw = *(const float4*)(conv_w + c * DCONV);
            const float  cb = conv_b[c];
            const __half* raw = (const __half*)(smem + (kc & 3) * RSTG);
            __half* amma = (__half*)(smem + AMMA_OFF);
            #pragma unroll 4
            for (int i = 0; i < 16; i++) {
                int r = cg * 16 + i;          // token row in tile
                int rr = r + 3;               // raw row of token row0+r
                float v = cb;
                v += __half2float(raw[(rr - 3) * 32 + cch]) * cw.x;
                v += __half2float(raw[(rr - 2) * 32 + cch]) * cw.y;
                v += __half2float(raw[(rr - 1) * 32 + cch]) * cw.z;
                v += __half2float(raw[(rr    ) * 32 + cch]) * cw.w;
                float s = v / (1.f + __expf(-v));
                __half h = __float2half(s);
                amma[r * 40 + cch] = h;
                xi[(size_t)(row0 + r) * DINNER + c] = h;
            }
        }
        __syncthreads();               // Amma tile ready

        uint32_t abase = sb + AMMA_OFF;
        #pragma unroll
        for (int ks = 0; ks < 2; ks++) {
            uint32_t koff = (ks * 16 + lkb * 8) * 2;
            uint32_t ah[2][4];
            #pragma unroll
            for (int mi = 0; mi < 2; mi++)
                LDSM4(ah[mi], abase + (wm + mi * 16 + lrow) * 80 + koff);
            uint32_t bf[4][4];
            #pragma unroll
            for (int p = 0; p < 4; p++)
                LDSM4(bf[p], rawb + RAWA + (wn + p * 16 + lrow) * 80 + koff);
            #pragma unroll
            for (int mi = 0; mi < 2; mi++)
                #pragma unroll
                for (int p = 0; p < 4; p++)
                    #pragma unroll
                    for (int hb = 0; hb < 2; hb++)
                        MMA16816(acc[mi][p * 2 + hb], ah[mi], bf[p][hb], bf[p][hb + 2]);
        }
        // no extra sync: top-of-loop CP_WAIT+sync guards reuse
    }

    const int rb = row0 + wm + (lane >> 2);
    const int cb2 = wn + (lane & 3) * 2;
    #pragma unroll
    for (int mi = 0; mi < 2; mi++)
        #pragma unroll
        for (int ni = 0; ni < 8; ni++) {
            int c = cb2 + ni * 8;
            #pragma unroll
            for (int half = 0; half < 2; half++) {
                int r = rb + mi * 16 + half * 8;
                *(float2*)(Cf + (size_t)r * 128 + c) =
                    make_float2(acc[mi][ni][half * 2 + 0], acc[mi][ni][half * 2 + 1]);
            }
        }
}

// ---------------------------------------------------------------------------
// Split-K reduce for dbc + dt fp16
// ---------------------------------------------------------------------------
__global__ void reduce_dbc(const float* __restrict__ part,
                           float* __restrict__ dbc,
                           __half* __restrict__ dt) {
    int i = blockIdx.x * blockDim.x + threadIdx.x;
    int r = i >> 7, c = i & 127;
    float s = 0.f;
    #pragma unroll
    for (int p = 0; p < KSPLIT; p++)
        s += part[(size_t)p * NTOK * 128 + i];
    if (c < DBC_W) dbc[(size_t)r * DBC_W + c] = s;
    if (c < DTRANK) dt[(size_t)r * DTRANK + c] = __float2half(s);
}

// ---------------------------------------------------------------------------
// Scan pass 1 (128 threads = 128 channels/block): segment transfer
// ---------------------------------------------------------------------------
#define SCHUNK 16
#define SSTG1  9216                    // delta 4K | xi 4K | B 1K
__global__ __launch_bounds__(128, 1)
void scan_pass1(const float* __restrict__ dbc,
                const __half* __restrict__ delta,
                const __half* __restrict__ xi,
                const float* __restrict__ A_log,
                float* __restrict__ segsum,
                float* __restrict__ segc) {
    __shared__ char sbuf[4 * SSTG1];
    const uint32_t sb = smem_u32(sbuf);
    const int seg   = blockIdx.y;
    const int b     = blockIdx.x >> 4;
    const int cbase = (blockIdx.x & 15) * 128;
    const int tid   = threadIdx.x;
    const int c     = cbase + tid;
    const size_t tok0 = (size_t)b * LL + (size_t)seg * SEGLEN;

    float A[DSTATE];
    #pragma unroll
    for (int s = 0; s < DSTATE; s++) A[s] = -__expf(A_log[c * DSTATE + s]);
    const float a1 = A[0];
    bool pat = true;
    #pragma unroll
    for (int s = 0; s < DSTATE; s++)
        pat = pat && (fabsf(A[s] - (float)(s + 1) * a1) <= 1e-5f * fabsf(A[s]));

    float h[DSTATE];
    #pragma unroll
    for (int s = 0; s < DSTATE; s++) h[s] = 0.f;
    float sd = 0.f;

    auto stage_load = [&](int st, int l0) {
        uint32_t base = sb + st * SSTG1;
        #pragma unroll
        for (int u0 = 0; u0 < 5; u0++) {
            int u = u0 * 128 + tid;
            if (u >= 576) break;
            uint32_t dst; const void* src;
            if (u < 256) {
                int r = u >> 4, s = u & 15;
                dst = base + r * 256 + s * 16;
                src = delta + (tok0 + l0 + r) * DINNER + cbase + s * 8;
            } else if (u < 512) {
                int v = u - 256; int r = v >> 4, s = v & 15;
                dst = base + 4096 + r * 256 + s * 16;
                src = xi + (tok0 + l0 + r) * DINNER + cbase + s * 8;
            } else {
                int v = u - 512; int r = v >> 2, s = v & 3;
                dst = base + 8192 + r * 64 + s * 16;
                src = dbc + (tok0 + l0 + r) * DBC_W + DTRANK + s * 4;
            }
            cp16(dst, src);
        }
    };

    const int nch = SEGLEN / SCHUNK;
    stage_load(0, 0);          CP_COMMIT();
    stage_load(1, SCHUNK);     CP_COMMIT();
    stage_load(2, 2 * SCHUNK); CP_COMMIT();

    for (int ck = 0; ck < nch; ck++) {
        CP_WAIT(2);
        __syncthreads();
        if (ck + 3 < nch) stage_load((ck + 3) & 3, (ck + 3) * SCHUNK);
        CP_COMMIT();

        const char* base = sbuf + (ck & 3) * SSTG1;
        const __half* sd16 = (const __half*)(base);
        const __half* sxi  = (const __half*)(base + 4096);
        const float*  sB   = (const float*)(base + 8192);

        #pragma unroll 4
        for (int l = 0; l < SCHUNK; l++) {
            float d  = __half2float(sd16[l * 128 + tid]);
            float xv = __half2float(sxi[l * 128 + tid]);
            const float* Bv = sB + l * 16;
            float dx = d * xv;
            if (pat) {
                float P[DSTATE];
                exp_powers(__expf(d * a1), P);
                #pragma unroll
                for (int s = 0; s < DSTATE; s++)
                    h[s] = P[s] * h[s] + dx * Bv[s];
            } else {
                #pragma unroll
                for (int s = 0; s < DSTATE; s++)
                    h[s] = __expf(d * A[s]) * h[s] + dx * Bv[s];
            }
            sd += d;
        }
        __syncthreads();
    }

    size_t bc = (size_t)seg * BB * DINNER + (size_t)b * DINNER + c;
    segsum[bc] = sd;
    #pragma unroll
    for (int s = 0; s < DSTATE; s++)
        segc[bc * DSTATE + s] = h[s];
}

// ---------------------------------------------------------------------------
// Scan pass 2 (128 threads): fold prefix segments, run SEGLEN steps.
// z half of xz already holds silu(z).
// ---------------------------------------------------------------------------
#define SSTG2  14336                   // delta 4K | sz 4K | xi 4K | bc 2K
__global__ __launch_bounds__(128, 1)
void scan_pass2(const float* __restrict__ dbc,
                const __half* __restrict__ delta,
                const __half* __restrict__ xi,
                const __half* __restrict__ xz,
                const float* __restrict__ A_log,
                const float* __restrict__ Dp,
                const float* __restrict__ segsum,
                const float* __restrict__ segc,
                __half* __restrict__ gout) {
    __shared__ char sbuf[4 * SSTG2];
    const uint32_t sb = smem_u32(sbuf);
    const int seg   = blockIdx.y;
    const int b     = blockIdx.x >> 4;
    const int cbase = (blockIdx.x & 15) * 128;
    const int tid   = threadIdx.x;
    const int c     = cbase + tid;
    const size_t tok0 = (size_t)b * LL + (size_t)seg * SEGLEN;

    float A[DSTATE];
    #pragma unroll
    for (int s = 0; s < DSTATE; s++) A[s] = -__expf(A_log[c * DSTATE + s]);
    const float a1 = A[0];
    bool pat = true;
    #pragma unroll
    for (int s = 0; s < DSTATE; s++)
        pat = pat && (fabsf(A[s] - (float)(s + 1) * a1) <= 1e-5f * fabsf(A[s]));
    const float Dv = Dp[c];

    float h[DSTATE];
    #pragma unroll
    for (int s = 0; s < DSTATE; s++) h[s] = 0.f;
    for (int j = 0; j < seg; j++) {
        size_t bc = (size_t)j * BB * DINNER + (size_t)b * DINNER + c;
        float sdj = segsum[bc];
        if (pat) {
            float P[DSTATE];
            exp_powers(__expf(sdj * a1), P);
            #pragma unroll
            for (int s = 0; s < DSTATE; s++)
                h[s] = P[s] * h[s] + segc[bc * DSTATE + s];
        } else {
            #pragma unroll
            for (int s = 0; s < DSTATE; s++)
                h[s] = __expf(sdj * A[s]) * h[s] + segc[bc * DSTATE + s];
        }
    }

    auto stage_load = [&](int st, int l0) {
        uint32_t base = sb + st * SSTG2;
        #pragma unroll
        for (int u0 = 0; u0 < 7; u0++) {
            int u = u0 * 128 + tid;
            if (u >= 896) break;
            uint32_t dst; const void* src;
            if (u < 256) {
                int r = u >> 4, s = u & 15;
                dst = base + r * 256 + s * 16;
                src = delta + (tok0 + l0 + r) * DINNER + cbase + s * 8;
            } else if (u < 512) {
                int v = u - 256; int r = v >> 4, s = v & 15;
                dst = base + 4096 + r * 256 + s * 16;
                src = xz + (tok0 + l0 + r) * (2 * DINNER) + DINNER + cbase + s * 8;
            } else if (u < 768) {
                int v = u - 512; int r = v >> 4, s = v & 15;
                dst = base + 8192 + r * 256 + s * 16;
                src = xi + (tok0 + l0 + r) * DINNER + cbase + s * 8;
            } else {
                int v = u - 768; int r = v >> 3, s = v & 7;
                dst = base + 12288 + r * 128 + s * 16;
                src = dbc + (tok0 + l0 + r) * DBC_W + DTRANK + s * 4;
            }
            cp16(dst, src);
        }
    };

    const int nch = SEGLEN / SCHUNK;
    stage_load(0, 0);          CP_COMMIT();
    stage_load(1, SCHUNK);     CP_COMMIT();
    stage_load(2, 2 * SCHUNK); CP_COMMIT();

    for (int ck = 0; ck < nch; ck++) {
        CP_WAIT(2);
        __syncthreads();
        if (ck + 3 < nch) stage_load((ck + 3) & 3, (ck + 3) * SCHUNK);
        CP_COMMIT();

        const char* base = sbuf + (ck & 3) * SSTG2;
        const __half* sd16 = (const __half*)(base);
        const __half* ssg  = (const __half*)(base + 4096);
        const __half* sxi  = (const __half*)(base + 8192);
        const float*  sbc  = (const float*)(base + 12288);
        const int l0 = ck * SCHUNK;

        #pragma unroll 4
        for (int l = 0; l < SCHUNK; l++) {
            float d  = __half2float(sd16[l * 128 + tid]);
            float sg = __half2float(ssg[l * 128 + tid]);
            float xv = __half2float(sxi[l * 128 + tid]);
            const float* Bv = sbc + l * 32;
            const float* Cv = Bv + DSTATE;
            float dx = d * xv;
            float y = 0.f;
            if (pat) {
                float P[DSTATE];
                exp_powers(__expf(d * a1), P);
                #pragma unroll
                for (int s = 0; s < DSTATE; s++) {
                    h[s] = P[s] * h[s] + dx * Bv[s];
                    y = fmaf(h[s], Cv[s], y);
                }
            } else {
                #pragma unroll
                for (int s = 0; s < DSTATE; s++) {
                    h[s] = __expf(d * A[s]) * h[s] + dx * Bv[s];
                    y = fmaf(h[s], Cv[s], y);
                }
            }
            float g = y + xv * Dv;
            gout[(tok0 + l0 + l) * DINNER + c] = __float2half(g * sg);
        }
        __syncthreads();
    }
}

// ---------------------------------------------------------------------------
// Launch
// ---------------------------------------------------------------------------
extern "C" void kernel_launch(void* const* d_in, const int* in_sizes, int n_in,
                              void* d_out, int out_size) {
    const float* x        = (const float*)d_in[0];
    const float* rms_w    = (const float*)d_in[1];
    const float* in_proj  = (const float*)d_in[2];
    const float* conv_w   = (const float*)d_in[3];
    const float* conv_b   = (const float*)d_in[4];
    const float* x_proj   = (const float*)d_in[5];
    const float* dt_w     = (const float*)d_in[6];
    const float* dt_b     = (const float*)d_in[7];
    const float* A_log    = (const float*)d_in[8];
    const float* Dp       = (const float*)d_in[9];
    const float* out_proj = (const float*)d_in[10];
    float* out = (float*)d_out;

    float *dbc, *dbcp, *segsum, *segc;
    __half *xz, *delta, *xn, *xi, *dt, *gg, *ipT, *xpT, *dwT, *opT;
    cudaGetSymbolAddress((void**)&xz,     g_xz);
    cudaGetSymbolAddress((void**)&dbc,    g_dbc);
    cudaGetSymbolAddress((void**)&dbcp,   g_dbcp);
    cudaGetSymbolAddress((void**)&delta,  g_delta);
    cudaGetSymbolAddress((void**)&xn,     g_xn);
    cudaGetSymbolAddress((void**)&xi,     g_xi);
    cudaGetSymbolAddress((void**)&dt,     g_dt);
    cudaGetSymbolAddress((void**)&gg,     g_g);
    cudaGetSymbolAddress((void**)&segsum, g_segsum);
    cudaGetSymbolAddress((void**)&segc,   g_segc);
    cudaGetSymbolAddress((void**)&ipT,    g_ipT);
    cudaGetSymbolAddress((void**)&xpT,    g_xpT);
    cudaGetSymbolAddress((void**)&dwT,    g_dwT);
    cudaGetSymbolAddress((void**)&opT,    g_opT);

    cudaFuncSetAttribute(mma_gemm<1>, cudaFuncAttributeMaxDynamicSharedMemorySize, SMEM_GEMM);
    cudaFuncSetAttribute(mma_gemm<2>, cudaFuncAttributeMaxDynamicSharedMemorySize, SMEM_GEMM);
    cudaFuncSetAttribute(mma_gemm<4>, cudaFuncAttributeMaxDynamicSharedMemorySize, SMEM_GEMM);
    cudaFuncSetAttribute(gemm2_fused, cudaFuncAttributeMaxDynamicSharedMemorySize, SMEM_G2);

    // 0+1. fused prep: 4 weight transposes + rmsnorm in ONE launch
    prep_kernel<<<6464 + NTOK, 256>>>(in_proj, x_proj, dt_w, out_proj,
                                      ipT, xpT, dwT, opT, x, rms_w, xn);

    // 2. xz = xn @ in_proj -> fp16 (z half stored as silu(z))
    {
        dim3 grid(2 * DINNER / 128, NTOK / 128);
        mma_gemm<4><<<grid, 256, SMEM_GEMM>>>(xn, ipT, xz, 2 * DINNER, DIM, DIM,
                                              nullptr);
    }

    // 3+4. conv+silu fused into split-K dbc GEMM (writes xi + partials) + reduce
    {
        dim3 grid(1, NTOK / 128, KSPLIT);
        gemm2_fused<<<grid, 256, SMEM_G2>>>(xz, xpT, conv_w, conv_b, xi, dbcp);
        reduce_dbc<<<NTOK * 128 / 256, 256>>>(dbcp, dbc, dt);
    }

    // 5. delta = softplus(dt @ dt_w + dt_b) -> fp16  [8192 x 2048], K=64
    {
        dim3 grid(DINNER / 128, NTOK / 128);
        mma_gemm<1><<<grid, 256, SMEM_GEMM>>>(dt, dwT, delta, DINNER, DTRANK, DTRANK,
                                              dt_b);
    }

    // 6. parallel selective scan (2 passes, 128-thread blocks)
    {
        dim3 g1(BB * (DINNER / 128), NSEG - 1);
        scan_pass1<<<g1, 128>>>(dbc, delta, xi, A_log, segsum, segc);
        dim3 g2(BB * (DINNER / 128), NSEG);
        scan_pass2<<<g2, 128>>>(dbc, delta, xi, xz, A_log, Dp, segsum, segc, gg);
    }

    // 7. out = x + gated @ out_proj  [8192 x 1024], K=2048
    {
        dim3 grid(DIM / 128, NTOK / 128);
        mma_gemm<2><<<grid, 256, SMEM_GEMM>>>(gg, opT, out, DIM, DINNER, DINNER,
                                              x);
    }
}